// round 1
// baseline (speedup 1.0000x reference)
#include <cuda_runtime.h>
#include <cstdint>

// Problem constants
#define SN 256        // batch == seq_len
#define EE 1024       // embedding dim
#define HH 10         // hidden dim
#define NG 40         // 4 gates * H
#define TT 50         // tagset size
#define NP (SN*SN)    // 65536 rows (t,b)
#define WG_STRIDE 10340  // (E+H)*H per gate

// Phase A tiling
#define BK 32
#define MT 256
#define ATHREADS 128

// Scratch (no allocations allowed -> device globals)
__device__ float g_base[(size_t)NP * NG];   // x@Wx + bg + theta, per (t,b,gate,h)
__device__ float g_hx[(size_t)NP * HH];     // hx outputs of the scan

// ---------- packed f32x2 helpers (sm_103a FFMA2) ----------
__device__ __forceinline__ unsigned long long pk2(float lo, float hi) {
    unsigned long long r;
    asm("mov.b64 %0, {%1,%2};" : "=l"(r) : "f"(lo), "f"(hi));
    return r;
}
__device__ __forceinline__ void fma2(unsigned long long &d, unsigned long long a, unsigned long long b) {
    asm("fma.rn.f32x2 %0, %1, %2, %3;" : "=l"(d) : "l"(a), "l"(b), "l"(d));
}
__device__ __forceinline__ void upk2(unsigned long long v, float &lo, float &hi) {
    asm("mov.b64 {%0,%1}, %2;" : "=f"(lo), "=f"(hi) : "l"(v));
}
__device__ __forceinline__ void cp16(uint32_t dst, const void* src) {
    asm volatile("cp.async.cg.shared.global [%0], [%1], 16;" :: "r"(dst), "l"(src) : "memory");
}

// =========================================================================
// Phase A: gathered skinny GEMM  base[p][col] = emb[tok[p]] . Wg[col/10][:1024][col%10] + bg + theta
// Block: 256 rows x 40 cols, 128 threads, K chunks of 32, cp.async double buffer.
// Per thread: 8 rows (4 f32x2 pairs) x 10 cols.
// =========================================================================
extern __shared__ char smem_raw[];

__global__ __launch_bounds__(ATHREADS, 2) void phaseA_kernel(
    const int* __restrict__ tok, const float* __restrict__ emb,
    const float* __restrict__ Wg, const float* __restrict__ bg,
    const float* __restrict__ theta)
{
    float*  sA   = (float*)smem_raw;                                  // 2 * MT * BK floats (64 KB), XOR-swizzled
    float2* sB   = (float2*)(smem_raw + 2*MT*BK*sizeof(float));       // 2 * BK * NG duplicated float2 (20 KB)
    int*    stok = (int*)(smem_raw + 2*MT*BK*sizeof(float) + 2*BK*NG*sizeof(float2));

    const int tid = threadIdx.x;
    const int rowbase = blockIdx.x * MT;

    for (int i = tid; i < MT; i += ATHREADS) stok[i] = tok[rowbase + i];
    __syncthreads();

    const int rg  = tid >> 2;    // 0..31 -> rows rg*8..rg*8+7
    const int cg  = tid & 3;     // 0..3  -> cols cg*10..cg*10+9
    const int rgx = rg & 7;      // swizzle key (== (row>>3)&7 for this thread's rows)

    unsigned long long acc[4][10];
#pragma unroll
    for (int p = 0; p < 4; p++)
#pragma unroll
        for (int c = 0; c < 10; c++) acc[p][c] = 0ull;

    // stage B chunk 0 into regs
    float breg[10];
#pragma unroll
    for (int i = 0; i < 10; i++) {
        int e = i * ATHREADS + tid;          // 0..1279
        int k = e / NG, col = e % NG;
        breg[i] = Wg[(col / HH) * WG_STRIDE + k * HH + (col % HH)];
    }

    const uint32_t sA_base = (uint32_t)__cvta_generic_to_shared(sA);

    // issue A chunk 0 (cp.async, 16B, XOR-swizzled by (row>>3)&7)
#pragma unroll
    for (int it = 0; it < 16; it++) {
        int idx = it * ATHREADS + tid;       // 0..2047 16B-chunks
        int row = idx >> 3, c = idx & 7;
        uint32_t dst = sA_base + (uint32_t)((row * BK + ((c ^ ((row >> 3) & 7)) << 2)) * 4);
        const float* src = emb + (size_t)stok[row] * EE + (c << 2);
        cp16(dst, src);
    }
    asm volatile("cp.async.commit_group;" ::: "memory");

    for (int ch = 0; ch < EE / BK; ch++) {
        const int buf = ch & 1;

        // write staged B chunk into smem (duplicated pairs for FFMA2)
#pragma unroll
        for (int i = 0; i < 10; i++) {
            int e = i * ATHREADS + tid;
            int k = e / NG, col = e % NG;
            sB[buf * BK * NG + k * NG + col] = make_float2(breg[i], breg[i]);
        }
        // stage next B chunk
        if (ch + 1 < EE / BK) {
            int k0n = (ch + 1) * BK;
#pragma unroll
            for (int i = 0; i < 10; i++) {
                int e = i * ATHREADS + tid;
                int k = e / NG, col = e % NG;
                breg[i] = Wg[(col / HH) * WG_STRIDE + (k0n + k) * HH + (col % HH)];
            }
        }

        asm volatile("cp.async.wait_group 0;" ::: "memory");
        __syncthreads();   // A chunk ch in smem; prior compute on the other buffer finished

        // issue A chunk ch+1 (safe: its buffer's readers finished before the barrier)
        if (ch + 1 < EE / BK) {
            int k0n = (ch + 1) * BK;
            int nbuf = 1 - buf;
#pragma unroll
            for (int it = 0; it < 16; it++) {
                int idx = it * ATHREADS + tid;
                int row = idx >> 3, c = idx & 7;
                uint32_t dst = sA_base + (uint32_t)((nbuf * MT * BK + row * BK + ((c ^ ((row >> 3) & 7)) << 2)) * 4);
                const float* src = emb + (size_t)stok[row] * EE + k0n + (c << 2);
                cp16(dst, src);
            }
            asm volatile("cp.async.commit_group;" ::: "memory");
        }

        // compute on buffer `buf`
        const float*  A = sA + buf * MT * BK;
        const float2* B = sB + buf * BK * NG;
#pragma unroll 4
        for (int k = 0; k < BK; k++) {
            float av[8];
#pragma unroll
            for (int i = 0; i < 8; i++) {
                int row = rg * 8 + i;
                av[i] = A[row * BK + (((k >> 2) ^ rgx) << 2) + (k & 3)];
            }
            unsigned long long ap[4];
#pragma unroll
            for (int p = 0; p < 4; p++) ap[p] = pk2(av[2 * p], av[2 * p + 1]);
#pragma unroll
            for (int c = 0; c < 10; c++) {
                unsigned long long bv =
                    *(const unsigned long long*)&B[k * NG + cg * 10 + c];
#pragma unroll
                for (int p = 0; p < 4; p++) fma2(acc[p][c], ap[p], bv);
            }
        }
        // no trailing barrier needed: next iter's barrier separates buffers correctly
    }

    // epilogue: add bg + theta, store
    float cb[10];
#pragma unroll
    for (int c = 0; c < 10; c++) {
        int col = cg * 10 + c;
        cb[c] = bg[col] + theta[col];
    }
#pragma unroll
    for (int p = 0; p < 4; p++) {
        int r0 = rowbase + rg * 8 + 2 * p;
#pragma unroll
        for (int c = 0; c < 10; c++) {
            float lo, hi;
            upk2(acc[p][c], lo, hi);
            g_base[(size_t)r0 * NG + cg * 10 + c]       = lo + cb[c];
            g_base[(size_t)(r0 + 1) * NG + cg * 10 + c] = hi + cb[c];
        }
    }
}

// =========================================================================
// Phase B: 256 independent LSTM chains over t. 2 chains per warp (width-16
// shuffle groups), lane l = hidden unit h (l<10 active), all 4 gates per lane.
// =========================================================================
__device__ __forceinline__ float sigm_(float x) {
    float e = __expf(-x);
    return __fdividef(1.f, 1.f + e);
}
__device__ __forceinline__ float tanh_(float x) {
    float e = __expf(2.f * x);                  // inf for large x -> result 1; 0 for very neg -> -1
    return 1.f - __fdividef(2.f, 1.f + e);
}
// qlayer closed form: out_0 = prod_{j>=1} cos(a_j); out_w = prod_{j<=w} cos(a_j)
__device__ __forceinline__ float qlayer_(float a, int l) {
    float c = __cosf(a);
    float d = (l == 0) ? 1.f : c;               // mask lane 0 so scan gives prod_{1..l}
#pragma unroll
    for (int off = 1; off < 16; off <<= 1) {
        float v = __shfl_up_sync(0xffffffffu, d, off, 16);
        if (l >= off) d *= v;
    }
    float c0 = __shfl_sync(0xffffffffu, c, 0, 16);
    float q9 = __shfl_sync(0xffffffffu, d, HH - 1, 16);
    return (l == 0) ? q9 : c0 * d;
}

__global__ __launch_bounds__(32) void phaseB_kernel(const float* __restrict__ Wg)
{
    const int lane = threadIdx.x;
    const int grp  = lane >> 4;
    const int l    = lane & 15;
    const int b    = blockIdx.x * 2 + grp;
    const bool on  = (l < HH);

    // recurrent weights Wh[g][j] for this lane's h
    float w0[HH], w1[HH], w2[HH], w3[HH];
#pragma unroll
    for (int j = 0; j < HH; j++) {
        w0[j] = on ? Wg[0 * WG_STRIDE + (EE + j) * HH + l] : 0.f;
        w1[j] = on ? Wg[1 * WG_STRIDE + (EE + j) * HH + l] : 0.f;
        w2[j] = on ? Wg[2 * WG_STRIDE + (EE + j) * HH + l] : 0.f;
        w3[j] = on ? Wg[3 * WG_STRIDE + (EE + j) * HH + l] : 0.f;
    }

    float hx = 0.f, cx = 0.f;
    float nb0, nb1, nb2, nb3;
    {
        const float* bp = g_base + (size_t)b * NG + l;
        nb0 = on ? bp[0]  : 0.f;
        nb1 = on ? bp[10] : 0.f;
        nb2 = on ? bp[20] : 0.f;
        nb3 = on ? bp[30] : 0.f;
    }

#pragma unroll 1
    for (int t = 0; t < SN; t++) {
        float a0 = nb0, a1 = nb1, a2 = nb2, a3 = nb3;
        if (t + 1 < SN) {                        // prefetch next step's base
            const float* bp = g_base + ((size_t)(t + 1) * SN + b) * NG + l;
            nb0 = on ? bp[0]  : 0.f;
            nb1 = on ? bp[10] : 0.f;
            nb2 = on ? bp[20] : 0.f;
            nb3 = on ? bp[30] : 0.f;
        }
#pragma unroll
        for (int j = 0; j < HH; j++) {
            float hj = __shfl_sync(0xffffffffu, hx, j, 16);
            a0 = fmaf(hj, w0[j], a0);
            a1 = fmaf(hj, w1[j], a1);
            a2 = fmaf(hj, w2[j], a2);
            a3 = fmaf(hj, w3[j], a3);
        }
        float qf = qlayer_(a0, l);
        float qi = qlayer_(a1, l);
        float qg = qlayer_(a2, l);
        float qo = qlayer_(a3, l);

        float f  = sigm_(qf);
        float ii = sigm_(qi);
        float gg = tanh_(qg);
        float o  = sigm_(qo);

        cx = f * cx + ii * gg;
        hx = o * tanh_(cx);

        if (on) g_hx[((size_t)t * SN + b) * HH + l] = hx;
    }
}

// =========================================================================
// Phase C: logits = hx @ W_out + b_out, then log_softmax over T=50.
// One row per thread.
// =========================================================================
__global__ __launch_bounds__(128) void phaseC_kernel(
    const float* __restrict__ Wout, const float* __restrict__ bout,
    float* __restrict__ out)
{
    __shared__ float sW[HH * TT];
    __shared__ float sb[TT];
    const int tid = threadIdx.x;
    for (int i = tid; i < HH * TT; i += 128) sW[i] = Wout[i];
    for (int i = tid; i < TT;      i += 128) sb[i] = bout[i];
    __syncthreads();

    const int row = blockIdx.x * 128 + tid;
    float h[HH];
#pragma unroll
    for (int j = 0; j < HH; j++) h[j] = g_hx[(size_t)row * HH + j];

    float lg[TT];
#pragma unroll
    for (int c = 0; c < TT; c++) {
        float s = sb[c];
#pragma unroll
        for (int j = 0; j < HH; j++) s = fmaf(h[j], sW[j * TT + c], s);
        lg[c] = s;
    }
    float m = lg[0];
#pragma unroll
    for (int c = 1; c < TT; c++) m = fmaxf(m, lg[c]);
    float sum = 0.f;
#pragma unroll
    for (int c = 0; c < TT; c++) sum += __expf(lg[c] - m);
    float ls = m + __logf(sum);

    float* op = out + (size_t)row * TT;
#pragma unroll
    for (int c = 0; c < TT; c++) op[c] = lg[c] - ls;
}

// =========================================================================
extern "C" void kernel_launch(void* const* d_in, const int* in_sizes, int n_in,
                              void* d_out, int out_size)
{
    const int*   tok   = (const int*)d_in[0];     // sentence (256,256) int32
    const float* emb   = (const float*)d_in[1];   // (V, E)
    const float* Wg    = (const float*)d_in[2];   // (4, E+H, H)
    const float* bg    = (const float*)d_in[3];   // (4, H)
    const float* theta = (const float*)d_in[4];   // (4, H)
    const float* Wout  = (const float*)d_in[5];   // (H, T)
    const float* bout  = (const float*)d_in[6];   // (T)
    float* out = (float*)d_out;                   // (256,256,50) float32

    const size_t smemA = 2 * MT * BK * sizeof(float)
                       + 2 * BK * NG * sizeof(float2)
                       + MT * sizeof(int);        // 87,040 B
    cudaFuncSetAttribute(phaseA_kernel, cudaFuncAttributeMaxDynamicSharedMemorySize, (int)smemA);

    phaseA_kernel<<<NP / MT, ATHREADS, smemA>>>(tok, emb, Wg, bg, theta);
    phaseB_kernel<<<SN / 2, 32>>>(Wg);
    phaseC_kernel<<<NP / 128, 128>>>(Wout, bout, out);
}

// round 2
// speedup vs baseline: 1.0554x; 1.0554x over previous
#include <cuda_runtime.h>
#include <cstdint>

// Problem constants
#define SN 256        // batch == seq_len
#define EE 1024       // embedding dim
#define HH 10         // hidden dim
#define NG 40         // 4 gates * H
#define TT 50         // tagset size
#define NP (SN*SN)    // 65536 rows (t,b)
#define WG_STRIDE 10340  // (E+H)*H per gate

// Phase A tiling
#define BK 32
#define MT 128        // rows per block
#define ATHREADS 128  // 4 rows x 10 cols per thread

// Scratch (no allocations allowed -> device globals)
__device__ float g_base[(size_t)NP * NG];   // x@Wx + bg + theta, per (t,b,gate,h)
__device__ float g_hx[(size_t)NP * HH];     // hx outputs of the scan

// ---------- packed f32x2 helpers (sm_103a FFMA2) ----------
__device__ __forceinline__ unsigned long long pk2(float lo, float hi) {
    unsigned long long r;
    asm("mov.b64 %0, {%1,%2};" : "=l"(r) : "f"(lo), "f"(hi));
    return r;
}
__device__ __forceinline__ void fma2(unsigned long long &d, unsigned long long a, unsigned long long b) {
    asm("fma.rn.f32x2 %0, %1, %2, %3;" : "=l"(d) : "l"(a), "l"(b), "l"(d));
}
__device__ __forceinline__ void upk2(unsigned long long v, float &lo, float &hi) {
    asm("mov.b64 {%0,%1}, %2;" : "=f"(lo), "=f"(hi) : "l"(v));
}
__device__ __forceinline__ void cp16(uint32_t dst, const void* src) {
    asm volatile("cp.async.cg.shared.global [%0], [%1], 16;" :: "r"(dst), "l"(src) : "memory");
}

// =========================================================================
// Phase A: gathered skinny GEMM.
// Block: 128 rows x 40 cols, 128 threads. Per thread: 4 rows x 10 cols.
// A read as LDS.128 of swizzled 16B chunks (conflict-free: 8 bank-groups x 4
// lanes x 4-deep = 4 phases). B read as LDS.128 of duplicated col pairs
// (broadcast, conflict-free).
// =========================================================================
extern __shared__ char smem_raw[];

__global__ __launch_bounds__(ATHREADS, 4) void phaseA_kernel(
    const int* __restrict__ tok, const float* __restrict__ emb,
    const float* __restrict__ Wg, const float* __restrict__ bg,
    const float* __restrict__ theta)
{
    float*  sA   = (float*)smem_raw;                                  // 2 * MT * BK floats (32 KB)
    float2* sB   = (float2*)(smem_raw + 2*MT*BK*sizeof(float));       // 2 * BK * NG float2 (20 KB)
    int*    stok = (int*)(smem_raw + 2*MT*BK*sizeof(float) + 2*BK*NG*sizeof(float2));

    const int tid = threadIdx.x;
    const int rowbase = blockIdx.x * MT;

    for (int i = tid; i < MT; i += ATHREADS) stok[i] = tok[rowbase + i];
    __syncthreads();

    const int rg  = tid >> 2;        // 0..31 -> rows rg*4..rg*4+3
    const int cg  = tid & 3;         // 0..3  -> cols cg*10..cg*10+9
    const int key = (rg >> 1) & 7;   // swizzle key == (row>>3)&7 for this thread's rows

    unsigned long long acc[2][10];
#pragma unroll
    for (int p = 0; p < 2; p++)
#pragma unroll
        for (int c = 0; c < 10; c++) acc[p][c] = 0ull;

    // stage B chunk 0 into regs
    float breg[10];
#pragma unroll
    for (int i = 0; i < 10; i++) {
        int e = i * ATHREADS + tid;          // 0..1279
        int k = e / NG, col = e % NG;
        breg[i] = Wg[(col / HH) * WG_STRIDE + k * HH + (col % HH)];
    }

    const uint32_t sA_base = (uint32_t)__cvta_generic_to_shared(sA);

    // issue A chunk 0 (cp.async, 16B, XOR-swizzled by (row>>3)&7)
#pragma unroll
    for (int it = 0; it < 8; it++) {
        int idx = it * ATHREADS + tid;       // 0..1023 16B-chunks
        int row = idx >> 3, c = idx & 7;
        uint32_t dst = sA_base + (uint32_t)((row * BK + ((c ^ ((row >> 3) & 7)) << 2)) * 4);
        const float* src = emb + (size_t)stok[row] * EE + (c << 2);
        cp16(dst, src);
    }
    asm volatile("cp.async.commit_group;" ::: "memory");

    for (int ch = 0; ch < EE / BK; ch++) {
        const int buf = ch & 1;

        // write staged B chunk into smem (duplicated pairs for FFMA2)
#pragma unroll
        for (int i = 0; i < 10; i++) {
            int e = i * ATHREADS + tid;
            int k = e / NG, col = e % NG;
            sB[buf * BK * NG + k * NG + col] = make_float2(breg[i], breg[i]);
        }
        // stage next B chunk
        if (ch + 1 < EE / BK) {
            int k0n = (ch + 1) * BK;
#pragma unroll
            for (int i = 0; i < 10; i++) {
                int e = i * ATHREADS + tid;
                int k = e / NG, col = e % NG;
                breg[i] = Wg[(col / HH) * WG_STRIDE + (k0n + k) * HH + (col % HH)];
            }
        }

        asm volatile("cp.async.wait_group 0;" ::: "memory");
        __syncthreads();   // A chunk ch in smem; prior compute on the other buffer finished

        // issue A chunk ch+1
        if (ch + 1 < EE / BK) {
            int k0n = (ch + 1) * BK;
            int nbuf = 1 - buf;
#pragma unroll
            for (int it = 0; it < 8; it++) {
                int idx = it * ATHREADS + tid;
                int row = idx >> 3, c = idx & 7;
                uint32_t dst = sA_base + (uint32_t)((nbuf * MT * BK + row * BK + ((c ^ ((row >> 3) & 7)) << 2)) * 4);
                const float* src = emb + (size_t)stok[row] * EE + k0n + (c << 2);
                cp16(dst, src);
            }
            asm volatile("cp.async.commit_group;" ::: "memory");
        }

        // compute on buffer `buf`
        const float*  A = sA + buf * MT * BK;
        const float2* B = sB + buf * BK * NG;
#pragma unroll
        for (int kb = 0; kb < 8; kb++) {
            float4 av[4];
#pragma unroll
            for (int i = 0; i < 4; i++)
                av[i] = *(const float4*)(A + (rg * 4 + i) * BK + ((kb ^ key) << 2));
#pragma unroll
            for (int kk = 0; kk < 4; kk++) {
                float a0k, a1k, a2k, a3k;
                if (kk == 0)      { a0k = av[0].x; a1k = av[1].x; a2k = av[2].x; a3k = av[3].x; }
                else if (kk == 1) { a0k = av[0].y; a1k = av[1].y; a2k = av[2].y; a3k = av[3].y; }
                else if (kk == 2) { a0k = av[0].z; a1k = av[1].z; a2k = av[2].z; a3k = av[3].z; }
                else              { a0k = av[0].w; a1k = av[1].w; a2k = av[2].w; a3k = av[3].w; }
                unsigned long long ap0 = pk2(a0k, a1k);
                unsigned long long ap1 = pk2(a2k, a3k);
                const int k = kb * 4 + kk;
                const ulonglong2* pb = (const ulonglong2*)(B + k * NG + cg * 10);
#pragma unroll
                for (int c2 = 0; c2 < 5; c2++) {
                    ulonglong2 q = pb[c2];      // LDS.128: (b,b,b2,b2)
                    fma2(acc[0][2*c2],     ap0, q.x);
                    fma2(acc[1][2*c2],     ap1, q.x);
                    fma2(acc[0][2*c2 + 1], ap0, q.y);
                    fma2(acc[1][2*c2 + 1], ap1, q.y);
                }
            }
        }
    }

    // epilogue: add bg + theta, store
    float cb[10];
#pragma unroll
    for (int c = 0; c < 10; c++) {
        int col = cg * 10 + c;
        cb[c] = bg[col] + theta[col];
    }
#pragma unroll
    for (int p = 0; p < 2; p++) {
        int r0 = rowbase + rg * 4 + 2 * p;
#pragma unroll
        for (int c = 0; c < 10; c++) {
            float lo, hi;
            upk2(acc[p][c], lo, hi);
            g_base[(size_t)r0 * NG + cg * 10 + c]       = lo + cb[c];
            g_base[(size_t)(r0 + 1) * NG + cg * 10 + c] = hi + cb[c];
        }
    }
}

// =========================================================================
// Phase B: one LSTM chain per warp. Lanes 0-15: gates (f,i); lanes 16-31:
// gates (g,o). Each half-warp scan instruction carries two gates' data, so
// the per-step shuffle count drops to 24 and the critical path to one
// dual-register scan pass. Both halves compute identical hx/cx (replicated).
// =========================================================================
__global__ __launch_bounds__(32) void phaseB_kernel(const float* __restrict__ Wg)
{
    const int lane = threadIdx.x;
    const int grp  = lane >> 4;          // 0: f,i   1: g,o
    const int l    = lane & 15;
    const int b    = blockIdx.x;
    const bool on  = (l < HH);

    const int gA = grp ? 2 : 0;          // f or g
    const int gB = grp ? 3 : 1;          // i or o

    float wA[HH], wB[HH];
#pragma unroll
    for (int j = 0; j < HH; j++) {
        wA[j] = on ? Wg[gA * WG_STRIDE + (EE + j) * HH + l] : 0.f;
        wB[j] = on ? Wg[gB * WG_STRIDE + (EE + j) * HH + l] : 0.f;
    }

    // branch-free activation for gate A: grp0 -> sigmoid, grp1 -> tanh
    //   act = ca / (1 + exp(-sa*x)) + cbk
    const float sa  = grp ? 2.f : 1.f;
    const float ca  = grp ? 2.f : 1.f;
    const float cbk = grp ? -1.f : 0.f;

    float hx = 0.f, cx = 0.f;
    const float* bpA = g_base + (size_t)b * NG + gA * 10 + l;
    const float* bpB = g_base + (size_t)b * NG + gB * 10 + l;
    const size_t tstride = (size_t)SN * NG;

    float nbA = on ? bpA[0] : 0.f;
    float nbB = on ? bpB[0] : 0.f;

#pragma unroll 1
    for (int t = 0; t < SN; t++) {
        float aA = nbA, aB = nbB;
        if (t + 1 < SN) {                        // prefetch next step's base (L2-resident)
            nbA = on ? bpA[(t + 1) * tstride] : 0.f;
            nbB = on ? bpB[(t + 1) * tstride] : 0.f;
        }
#pragma unroll
        for (int j = 0; j < HH; j++) {
            float hj = __shfl_sync(0xffffffffu, hx, j, 16);
            aA = fmaf(hj, wA[j], aA);
            aB = fmaf(hj, wB[j], aB);
        }
        // qlayer: dual scan (one shuffle stream, two registers)
        float cA = __cosf(aA), cB = __cosf(aB);
        float dA = (l == 0) ? 1.f : cA;
        float dB = (l == 0) ? 1.f : cB;
#pragma unroll
        for (int off = 1; off < 16; off <<= 1) {
            float vA = __shfl_up_sync(0xffffffffu, dA, off, 16);
            float vB = __shfl_up_sync(0xffffffffu, dB, off, 16);
            if (l >= off) { dA *= vA; dB *= vB; }
        }
        float c0A = __shfl_sync(0xffffffffu, cA, 0, 16);
        float c0B = __shfl_sync(0xffffffffu, cB, 0, 16);
        float q9A = __shfl_sync(0xffffffffu, dA, HH - 1, 16);
        float q9B = __shfl_sync(0xffffffffu, dB, HH - 1, 16);
        float qA = (l == 0) ? q9A : c0A * dA;
        float qB = (l == 0) ? q9B : c0B * dB;

        // activations
        float eA   = __expf(-sa * qA);
        float actA = fmaf(ca, __fdividef(1.f, 1.f + eA), cbk);   // f (grp0) / g (grp1)
        float eB   = __expf(-qB);
        float actB = __fdividef(1.f, 1.f + eB);                  // i (grp0) / o (grp1)

        // exchange halves: grp0 gets (g,o), grp1 gets (f,i)
        float xA = __shfl_xor_sync(0xffffffffu, actA, 16);
        float xB = __shfl_xor_sync(0xffffffffu, actB, 16);
        float f  = grp ? xA   : actA;
        float ii = grp ? xB   : actB;
        float gg = grp ? actA : xA;
        float o  = grp ? actB : xB;

        cx = fmaf(f, cx, ii * gg);
        float e2 = __expf(-2.f * cx);
        float th = fmaf(2.f, __fdividef(1.f, 1.f + e2), -1.f);   // tanh(cx)
        hx = o * th;

        if (on && grp == 0) g_hx[((size_t)t * SN + b) * HH + l] = hx;
    }
}

// =========================================================================
// Phase C: logits = hx @ W_out + b_out, then log_softmax over T=50.
// =========================================================================
__global__ __launch_bounds__(128) void phaseC_kernel(
    const float* __restrict__ Wout, const float* __restrict__ bout,
    float* __restrict__ out)
{
    __shared__ float sW[HH * TT];
    __shared__ float sb[TT];
    const int tid = threadIdx.x;
    for (int i = tid; i < HH * TT; i += 128) sW[i] = Wout[i];
    for (int i = tid; i < TT;      i += 128) sb[i] = bout[i];
    __syncthreads();

    const int row = blockIdx.x * 128 + tid;
    float h[HH];
#pragma unroll
    for (int j = 0; j < HH; j++) h[j] = g_hx[(size_t)row * HH + j];

    float lg[TT];
#pragma unroll
    for (int c = 0; c < TT; c++) {
        float s = sb[c];
#pragma unroll
        for (int j = 0; j < HH; j++) s = fmaf(h[j], sW[j * TT + c], s);
        lg[c] = s;
    }
    float m = lg[0];
#pragma unroll
    for (int c = 1; c < TT; c++) m = fmaxf(m, lg[c]);
    float sum = 0.f;
#pragma unroll
    for (int c = 0; c < TT; c++) sum += __expf(lg[c] - m);
    float ls = m + __logf(sum);

    float* op = out + (size_t)row * TT;
#pragma unroll
    for (int c = 0; c < TT; c++) op[c] = lg[c] - ls;
}

// =========================================================================
extern "C" void kernel_launch(void* const* d_in, const int* in_sizes, int n_in,
                              void* d_out, int out_size)
{
    const int*   tok   = (const int*)d_in[0];     // sentence (256,256) int32
    const float* emb   = (const float*)d_in[1];   // (V, E)
    const float* Wg    = (const float*)d_in[2];   // (4, E+H, H)
    const float* bg    = (const float*)d_in[3];   // (4, H)
    const float* theta = (const float*)d_in[4];   // (4, H)
    const float* Wout  = (const float*)d_in[5];   // (H, T)
    const float* bout  = (const float*)d_in[6];   // (T)
    float* out = (float*)d_out;                   // (256,256,50) float32

    const size_t smemA = 2 * MT * BK * sizeof(float)
                       + 2 * BK * NG * sizeof(float2)
                       + MT * sizeof(int);        // 53,760 B
    cudaFuncSetAttribute(phaseA_kernel, cudaFuncAttributeMaxDynamicSharedMemorySize, (int)smemA);

    phaseA_kernel<<<NP / MT, ATHREADS, smemA>>>(tok, emb, Wg, bg, theta);
    phaseB_kernel<<<SN, 32>>>(Wg);
    phaseC_kernel<<<NP / 128, 128>>>(Wout, bout, out);
}

// round 3
// speedup vs baseline: 1.3497x; 1.2789x over previous
#include <cuda_runtime.h>
#include <cstdint>

// Problem constants
#define SN 256        // batch == seq_len
#define EE 1024       // embedding dim
#define HH 10         // hidden dim
#define NG 40         // 4 gates * H
#define TT 50         // tagset size
#define NP (SN*SN)    // 65536 rows (t,b)
#define WG_STRIDE 10340  // (E+H)*H per gate

// Phase A tiling
#define BK 32         // k chunk
#define MT 128        // rows per block
#define ATHREADS 128  // 4 rows x 10 cols per thread
#define BTS 36        // padded k-stride of transposed B tile (16B aligned, bank-staggered)

// Scratch (no allocations allowed -> device globals)
__device__ float g_base[(size_t)NP * NG];   // x@Wx + bg + theta, per (t,b,gate,h)
__device__ float g_hx[(size_t)NP * HH];     // hx outputs of the scan

// ---------- packed f32x2 helpers (sm_103a FFMA2) ----------
__device__ __forceinline__ void fma2(unsigned long long &d, unsigned long long a, unsigned long long b) {
    asm("fma.rn.f32x2 %0, %1, %2, %3;" : "=l"(d) : "l"(a), "l"(b), "l"(d));
}
__device__ __forceinline__ void upk2(unsigned long long v, float &lo, float &hi) {
    asm("mov.b64 {%0,%1}, %2;" : "=f"(lo), "=f"(hi) : "l"(v));
}
__device__ __forceinline__ void cp16(uint32_t dst, const void* src) {
    asm volatile("cp.async.cg.shared.global [%0], [%1], 16;" :: "r"(dst), "l"(src) : "memory");
}
__device__ __forceinline__ int akey(int row) {            // A swizzle key: 8 distinct chunks per warp row-set
    return ((row >> 3) + (row & 7)) & 7;
}

// =========================================================================
// Phase A: gathered skinny GEMM  base[p][col] = emb[tok[p]] . Wg + bg + theta
// f32x2 packing over K: acc lanes hold (even-k, odd-k) partial sums.
// A: k-major smem rows, LDS.128 gives two (a_k,a_k+1) operands directly.
// B: transposed [col][k] smem (stride 36), LDS.128 gives (b_k..b_k+3).
// Inner loop per 4 k's: 14 LDS.128 + 80 FFMA2, zero packing movs.
// =========================================================================
extern __shared__ char smem_raw[];

__global__ __launch_bounds__(ATHREADS, 3) void phaseA_kernel(
    const int* __restrict__ tok, const float* __restrict__ emb,
    const float* __restrict__ Wg, const float* __restrict__ bg,
    const float* __restrict__ theta)
{
    float* sA  = (float*)smem_raw;                                   // 2 * MT * BK floats (32 KB)
    float* sBt = (float*)(smem_raw + 2*MT*BK*sizeof(float));         // 2 * NG * BTS floats (11.25 KB)
    int*   stok = (int*)(smem_raw + 2*MT*BK*sizeof(float) + 2*NG*BTS*sizeof(float));

    const int tid = threadIdx.x;
    const int rowbase = blockIdx.x * MT;

    for (int i = tid; i < MT; i += ATHREADS) stok[i] = tok[rowbase + i];
    __syncthreads();

    const int rg = tid >> 2;        // 0..31 -> rows rg*4..rg*4+3
    const int cg = tid & 3;         // 0..3  -> cols cg*10..cg*10+9

    int keyr[4];
#pragma unroll
    for (int r = 0; r < 4; r++) keyr[r] = akey(rg * 4 + r);

    unsigned long long acc[4][10];
#pragma unroll
    for (int r = 0; r < 4; r++)
#pragma unroll
        for (int c = 0; c < 10; c++) acc[r][c] = 0ull;

    // stage B chunk 0 into regs (k-major gather from Wg)
    float breg[10];
#pragma unroll
    for (int i = 0; i < 10; i++) {
        int e = i * ATHREADS + tid;          // 0..1279
        int k = e / NG, col = e % NG;
        breg[i] = Wg[(col / HH) * WG_STRIDE + k * HH + (col % HH)];
    }

    const uint32_t sA_base = (uint32_t)__cvta_generic_to_shared(sA);

    // issue A chunk 0 (cp.async 16B, XOR-swizzled chunks)
#pragma unroll
    for (int it = 0; it < 8; it++) {
        int idx = it * ATHREADS + tid;       // 0..1023 16B-chunks
        int row = idx >> 3, c = idx & 7;
        uint32_t dst = sA_base + (uint32_t)((row * BK + ((c ^ akey(row)) << 2)) * 4);
        const float* src = emb + (size_t)stok[row] * EE + (c << 2);
        cp16(dst, src);
    }
    asm volatile("cp.async.commit_group;" ::: "memory");

    for (int ch = 0; ch < EE / BK; ch++) {
        const int buf = ch & 1;

        // write staged B chunk transposed: sBt[col][k]
        float* Bw = sBt + buf * NG * BTS;
#pragma unroll
        for (int i = 0; i < 10; i++) {
            int e = i * ATHREADS + tid;
            int k = e / NG, col = e % NG;
            Bw[col * BTS + k] = breg[i];
        }
        // stage next B chunk
        if (ch + 1 < EE / BK) {
            int k0n = (ch + 1) * BK;
#pragma unroll
            for (int i = 0; i < 10; i++) {
                int e = i * ATHREADS + tid;
                int k = e / NG, col = e % NG;
                breg[i] = Wg[(col / HH) * WG_STRIDE + (k0n + k) * HH + (col % HH)];
            }
        }

        asm volatile("cp.async.wait_group 0;" ::: "memory");
        __syncthreads();   // A chunk + B transpose visible; prior buffer's readers done

        // issue A chunk ch+1 into the other buffer
        if (ch + 1 < EE / BK) {
            int k0n = (ch + 1) * BK;
            int nbuf = 1 - buf;
#pragma unroll
            for (int it = 0; it < 8; it++) {
                int idx = it * ATHREADS + tid;
                int row = idx >> 3, c = idx & 7;
                uint32_t dst = sA_base + (uint32_t)((nbuf * MT * BK + row * BK + ((c ^ akey(row)) << 2)) * 4);
                const float* src = emb + (size_t)stok[row] * EE + k0n + (c << 2);
                cp16(dst, src);
            }
            asm volatile("cp.async.commit_group;" ::: "memory");
        }

        // compute on buffer `buf`
        const float* A  = sA  + buf * MT * BK;
        const float* Bt = sBt + buf * NG * BTS;
#pragma unroll
        for (int kb = 0; kb < 8; kb++) {
            ulonglong2 a[4];
#pragma unroll
            for (int r = 0; r < 4; r++)
                a[r] = *(const ulonglong2*)(A + (rg * 4 + r) * BK + ((kb ^ keyr[r]) << 2));
#pragma unroll
            for (int h = 0; h < 2; h++) {            // col halves limit B liveness
                ulonglong2 bf[5];
#pragma unroll
                for (int c5 = 0; c5 < 5; c5++)
                    bf[c5] = *(const ulonglong2*)(Bt + (cg * 10 + h * 5 + c5) * BTS + kb * 4);
#pragma unroll
                for (int c5 = 0; c5 < 5; c5++)
#pragma unroll
                    for (int r = 0; r < 4; r++) {
                        fma2(acc[r][h * 5 + c5], a[r].x, bf[c5].x);
                        fma2(acc[r][h * 5 + c5], a[r].y, bf[c5].y);
                    }
            }
        }
    }

    // epilogue: lo+hi reduce, add bg + theta, store
    float cb[10];
#pragma unroll
    for (int c = 0; c < 10; c++) {
        int col = cg * 10 + c;
        cb[c] = bg[col] + theta[col];
    }
#pragma unroll
    for (int r = 0; r < 4; r++) {
        int row = rowbase + rg * 4 + r;
#pragma unroll
        for (int c = 0; c < 10; c++) {
            float lo, hi;
            upk2(acc[r][c], lo, hi);
            g_base[(size_t)row * NG + cg * 10 + c] = lo + hi + cb[c];
        }
    }
}

// =========================================================================
// Phase B: one LSTM chain per warp. Lanes 0-15: gates (f,i); lanes 16-31:
// gates (g,o). Dual-register half-warp scans; both halves replicate hx/cx.
// =========================================================================
__global__ __launch_bounds__(32) void phaseB_kernel(const float* __restrict__ Wg)
{
    const int lane = threadIdx.x;
    const int grp  = lane >> 4;          // 0: f,i   1: g,o
    const int l    = lane & 15;
    const int b    = blockIdx.x;
    const bool on  = (l < HH);

    const int gA = grp ? 2 : 0;          // f or g
    const int gB = grp ? 3 : 1;          // i or o

    float wA[HH], wB[HH];
#pragma unroll
    for (int j = 0; j < HH; j++) {
        wA[j] = on ? Wg[gA * WG_STRIDE + (EE + j) * HH + l] : 0.f;
        wB[j] = on ? Wg[gB * WG_STRIDE + (EE + j) * HH + l] : 0.f;
    }

    // branch-free activation for gate A: grp0 -> sigmoid, grp1 -> tanh
    const float sa  = grp ? 2.f : 1.f;
    const float ca  = grp ? 2.f : 1.f;
    const float cbk = grp ? -1.f : 0.f;

    float hx = 0.f, cx = 0.f;
    const float* bpA = g_base + (size_t)b * NG + gA * 10 + l;
    const float* bpB = g_base + (size_t)b * NG + gB * 10 + l;
    const size_t tstride = (size_t)SN * NG;

    float nbA = on ? bpA[0] : 0.f;
    float nbB = on ? bpB[0] : 0.f;

#pragma unroll 1
    for (int t = 0; t < SN; t++) {
        float aA = nbA, aB = nbB;
        if (t + 1 < SN) {                        // prefetch next step's base (L2-resident)
            nbA = on ? bpA[(t + 1) * tstride] : 0.f;
            nbB = on ? bpB[(t + 1) * tstride] : 0.f;
        }
#pragma unroll
        for (int j = 0; j < HH; j++) {
            float hj = __shfl_sync(0xffffffffu, hx, j, 16);
            aA = fmaf(hj, wA[j], aA);
            aB = fmaf(hj, wB[j], aB);
        }
        // qlayer: dual scan (one shuffle stream, two registers)
        float cA = __cosf(aA), cB = __cosf(aB);
        float dA = (l == 0) ? 1.f : cA;
        float dB = (l == 0) ? 1.f : cB;
#pragma unroll
        for (int off = 1; off < 16; off <<= 1) {
            float vA = __shfl_up_sync(0xffffffffu, dA, off, 16);
            float vB = __shfl_up_sync(0xffffffffu, dB, off, 16);
            if (l >= off) { dA *= vA; dB *= vB; }
        }
        float c0A = __shfl_sync(0xffffffffu, cA, 0, 16);
        float c0B = __shfl_sync(0xffffffffu, cB, 0, 16);
        float q9A = __shfl_sync(0xffffffffu, dA, HH - 1, 16);
        float q9B = __shfl_sync(0xffffffffu, dB, HH - 1, 16);
        float qA = (l == 0) ? q9A : c0A * dA;
        float qB = (l == 0) ? q9B : c0B * dB;

        // activations
        float eA   = __expf(-sa * qA);
        float actA = fmaf(ca, __fdividef(1.f, 1.f + eA), cbk);   // f (grp0) / g (grp1)
        float eB   = __expf(-qB);
        float actB = __fdividef(1.f, 1.f + eB);                  // i (grp0) / o (grp1)

        // exchange halves: grp0 gets (g,o), grp1 gets (f,i)
        float xA = __shfl_xor_sync(0xffffffffu, actA, 16);
        float xB = __shfl_xor_sync(0xffffffffu, actB, 16);
        float f  = grp ? xA   : actA;
        float ii = grp ? xB   : actB;
        float gg = grp ? actA : xA;
        float o  = grp ? actB : xB;

        cx = fmaf(f, cx, ii * gg);
        float e2 = __expf(-2.f * cx);
        float th = fmaf(2.f, __fdividef(1.f, 1.f + e2), -1.f);   // tanh(cx)
        hx = o * th;

        if (on && grp == 0) g_hx[((size_t)t * SN + b) * HH + l] = hx;
    }
}

// =========================================================================
// Phase C: logits = hx @ W_out + b_out, then log_softmax over T=50.
// =========================================================================
__global__ __launch_bounds__(128) void phaseC_kernel(
    const float* __restrict__ Wout, const float* __restrict__ bout,
    float* __restrict__ out)
{
    __shared__ float sW[HH * TT];
    __shared__ float sb[TT];
    const int tid = threadIdx.x;
    for (int i = tid; i < HH * TT; i += 128) sW[i] = Wout[i];
    for (int i = tid; i < TT;      i += 128) sb[i] = bout[i];
    __syncthreads();

    const int row = blockIdx.x * 128 + tid;
    float h[HH];
#pragma unroll
    for (int j = 0; j < HH; j++) h[j] = g_hx[(size_t)row * HH + j];

    float lg[TT];
#pragma unroll
    for (int c = 0; c < TT; c++) {
        float s = sb[c];
#pragma unroll
        for (int j = 0; j < HH; j++) s = fmaf(h[j], sW[j * TT + c], s);
        lg[c] = s;
    }
    float m = lg[0];
#pragma unroll
    for (int c = 1; c < TT; c++) m = fmaxf(m, lg[c]);
    float sum = 0.f;
#pragma unroll
    for (int c = 0; c < TT; c++) sum += __expf(lg[c] - m);
    float ls = m + __logf(sum);

    float2* op = (float2*)(out + (size_t)row * TT);
#pragma unroll
    for (int c = 0; c < TT / 2; c++)
        op[c] = make_float2(lg[2 * c] - ls, lg[2 * c + 1] - ls);
}

// =========================================================================
extern "C" void kernel_launch(void* const* d_in, const int* in_sizes, int n_in,
                              void* d_out, int out_size)
{
    const int*   tok   = (const int*)d_in[0];     // sentence (256,256) int32
    const float* emb   = (const float*)d_in[1];   // (V, E)
    const float* Wg    = (const float*)d_in[2];   // (4, E+H, H)
    const float* bg    = (const float*)d_in[3];   // (4, H)
    const float* theta = (const float*)d_in[4];   // (4, H)
    const float* Wout  = (const float*)d_in[5];   // (H, T)
    const float* bout  = (const float*)d_in[6];   // (T)
    float* out = (float*)d_out;                   // (256,256,50) float32

    const size_t smemA = 2 * MT * BK * sizeof(float)
                       + 2 * NG * BTS * sizeof(float)
                       + MT * sizeof(int);        // 44,800 B
    cudaFuncSetAttribute(phaseA_kernel, cudaFuncAttributeMaxDynamicSharedMemorySize, (int)smemA);

    phaseA_kernel<<<NP / MT, ATHREADS, smemA>>>(tok, emb, Wg, bg, theta);
    phaseB_kernel<<<SN, 32>>>(Wg);
    phaseC_kernel<<<NP / 128, 128>>>(Wout, bout, out);
}

// round 5
// speedup vs baseline: 1.3792x; 1.0219x over previous
#include <cuda_runtime.h>
#include <cstdint>

// Problem constants
#define SN 256        // batch == seq_len
#define EE 1024       // embedding dim
#define HH 10         // hidden dim
#define NG 40         // 4 gates * H
#define TT 50         // tagset size
#define NP (SN*SN)    // 65536 rows (t,b)
#define WG_STRIDE 10340  // (E+H)*H per gate

// Phase A tiling
#define BK 32         // k chunk
#define MT 128        // rows per block
#define ATHREADS 128  // 4 rows x 10 cols per thread
#define BTS 36        // padded k-stride of transposed B smem tile (144B, 16B aligned)
#define NCH (EE/BK)   // 32 chunks

// smem layout (bytes): stok [0,512); A [1024, 1024+2*16384); B [33792, +2*5760)
#define SM_STOK 0
#define SM_A    1024
#define SM_B    (SM_A + 2*MT*BK*4)          // 33792
#define SM_TOT  (SM_B + 2*NG*BTS*4)         // 45312

// Scratch (no allocations allowed -> device globals)
__device__ float g_base[(size_t)NP * NG];   // x@Wx + bg + theta
__device__ float g_hx[(size_t)NP * HH];     // hx outputs of the scan
__device__ float g_Bt[NCH * NG * BK];       // B transposed per chunk: [ch][col][k]

// ---------- helpers ----------
__device__ __forceinline__ void fma2(unsigned long long &d, unsigned long long a, unsigned long long b) {
    asm("fma.rn.f32x2 %0, %1, %2, %3;" : "=l"(d) : "l"(a), "l"(b), "l"(d));
}
__device__ __forceinline__ void upk2(unsigned long long v, float &lo, float &hi) {
    asm("mov.b64 {%0,%1}, %2;" : "=f"(lo), "=f"(hi) : "l"(v));
}
__device__ __forceinline__ void cp16(uint32_t dst, const void* src) {
    asm volatile("cp.async.cg.shared.global [%0], [%1], 16;" :: "r"(dst), "l"(src) : "memory");
}
__device__ __forceinline__ int akey(int row) {   // 8 distinct bank-groups per warp row-set
    return ((row >> 3) + (row & 7)) & 7;
}

// =========================================================================
// B pre-transpose: g_Bt[ch][col][k] (contiguous k runs of 32)
// =========================================================================
__global__ __launch_bounds__(256) void prepB_kernel(const float* __restrict__ Wg)
{
    int idx = blockIdx.x * 256 + threadIdx.x;          // 0..40959
    if (idx >= NCH * NG * BK) return;
    int ch = idx / (NG * BK);
    int r  = idx % (NG * BK);
    int col = r / BK, k = r % BK;
    g_Bt[idx] = Wg[(col / HH) * WG_STRIDE + (ch * BK + k) * HH + (col % HH)];
}

// =========================================================================
// Phase A: gathered skinny GEMM, FFMA2 with K-packing.
// 128 rows x 40 cols per CTA, 128 threads: 4 rows x 10 cols per thread.
// A: k-major smem rows, XOR-chunk swizzle, LDS.128 -> two (even,odd) f32x2.
// B: cp.async from pre-transposed global into [col][k] smem (stride 36).
// Double-buffered depth-1 cp.async pipeline; one barrier per chunk.
// =========================================================================
extern __shared__ char smem_raw[];

__global__ __launch_bounds__(ATHREADS, 4) void phaseA_kernel(
    const int* __restrict__ tok, const float* __restrict__ emb,
    const float* __restrict__ bg, const float* __restrict__ theta)
{
    int*   stok = (int*)(smem_raw + SM_STOK);
    float* sA   = (float*)(smem_raw + SM_A);
    float* sBt  = (float*)(smem_raw + SM_B);

    const int tid = threadIdx.x;
    const int rowbase = blockIdx.x * MT;

    if (tid < MT) stok[tid] = tok[rowbase + tid];
    __syncthreads();

    const int rg = tid >> 2;        // 0..31 -> rows rg*4..rg*4+3
    const int cg = tid & 3;         // 0..3  -> cols cg*10..cg*10+9

    int keyr[4];
#pragma unroll
    for (int r = 0; r < 4; r++) keyr[r] = akey(rg * 4 + r);

    unsigned long long acc[4][10];
#pragma unroll
    for (int r = 0; r < 4; r++)
#pragma unroll
        for (int c = 0; c < 10; c++) acc[r][c] = 0ull;

    const uint32_t sA_base = (uint32_t)__cvta_generic_to_shared(sA);
    const uint32_t sB_base = (uint32_t)__cvta_generic_to_shared(sBt);

    auto issue_chunk = [&](int ch) {
        const int s = ch & 1;
        const uint32_t abase = sA_base + (uint32_t)(s * MT * BK * 4);
        // A gather: 1024 16B chunks, 8/thread, XOR-swizzled
#pragma unroll
        for (int it = 0; it < 8; it++) {
            int idx = it * ATHREADS + tid;
            int row = idx >> 3, c = idx & 7;
            uint32_t dst = abase + (uint32_t)(row * (BK * 4) + ((c ^ akey(row)) << 4));
            cp16(dst, emb + (size_t)stok[row] * EE + ch * BK + (c << 2));
        }
        // B: 320 16B chunks linear from pre-transposed global
        const uint32_t bbase = sB_base + (uint32_t)(s * NG * BTS * 4);
        const float* bsrc = g_Bt + ch * (NG * BK);
#pragma unroll
        for (int it = 0; it < 3; it++) {
            int i = it * ATHREADS + tid;
            if (i < NG * 8) {
                int col = i >> 3, kq = i & 7;
                cp16(bbase + (uint32_t)(col * (BTS * 4) + (kq << 4)), bsrc + (i << 2));
            }
        }
        asm volatile("cp.async.commit_group;" ::: "memory");
    };

    issue_chunk(0);

    for (int ch = 0; ch < NCH; ch++) {
        asm volatile("cp.async.wait_group 0;" ::: "memory");  // chunk ch arrived
        __syncthreads();                                      // + compute(ch-1) done everywhere
        if (ch + 1 < NCH) issue_chunk(ch + 1);                // overlaps compute(ch)

        const int s = ch & 1;
        const float* A  = sA  + s * MT * BK;
        const float* Bt = sBt + s * NG * BTS;
#pragma unroll
        for (int kb = 0; kb < 8; kb++) {
            ulonglong2 a[4];
#pragma unroll
            for (int r = 0; r < 4; r++)
                a[r] = *(const ulonglong2*)(A + (rg * 4 + r) * BK + ((kb ^ keyr[r]) << 2));
#pragma unroll
            for (int h = 0; h < 2; h++) {            // col halves limit B liveness
                ulonglong2 bf[5];
#pragma unroll
                for (int c5 = 0; c5 < 5; c5++)
                    bf[c5] = *(const ulonglong2*)(Bt + (cg * 10 + h * 5 + c5) * BTS + kb * 4);
#pragma unroll
                for (int c5 = 0; c5 < 5; c5++)
#pragma unroll
                    for (int r = 0; r < 4; r++) {
                        fma2(acc[r][h * 5 + c5], a[r].x, bf[c5].x);
                        fma2(acc[r][h * 5 + c5], a[r].y, bf[c5].y);
                    }
            }
        }
    }

    // epilogue: lo+hi reduce, add bg + theta, store
    float cb[10];
#pragma unroll
    for (int c = 0; c < 10; c++) {
        int col = cg * 10 + c;
        cb[c] = bg[col] + theta[col];
    }
#pragma unroll
    for (int r = 0; r < 4; r++) {
        int row = rowbase + rg * 4 + r;
#pragma unroll
        for (int c = 0; c < 10; c++) {
            float lo, hi;
            upk2(acc[r][c], lo, hi);
            g_base[(size_t)row * NG + cg * 10 + c] = lo + hi + cb[c];
        }
    }
}

// =========================================================================
// Phase B: one LSTM chain per warp. Lanes 0-15: gates (f,i); lanes 16-31:
// gates (g,o). Dual-register half-warp scans; 4-step-deep LDG prefetch.
// =========================================================================
__global__ __launch_bounds__(32) void phaseB_kernel(const float* __restrict__ Wg)
{
    const int lane = threadIdx.x;
    const int grp  = lane >> 4;          // 0: f,i   1: g,o
    const int l    = lane & 15;
    const int b    = blockIdx.x;
    const bool on  = (l < HH);

    const int gA = grp ? 2 : 0;          // f or g
    const int gB = grp ? 3 : 1;          // i or o

    float wA[HH], wB[HH];
#pragma unroll
    for (int j = 0; j < HH; j++) {
        wA[j] = on ? Wg[gA * WG_STRIDE + (EE + j) * HH + l] : 0.f;
        wB[j] = on ? Wg[gB * WG_STRIDE + (EE + j) * HH + l] : 0.f;
    }

    const float sa  = grp ? 2.f : 1.f;
    const float ca  = grp ? 2.f : 1.f;
    const float cbk = grp ? -1.f : 0.f;

    float hx = 0.f, cx = 0.f;
    const float* bpA = g_base + (size_t)b * NG + gA * 10 + l;
    const float* bpB = g_base + (size_t)b * NG + gB * 10 + l;
    const size_t tstride = (size_t)SN * NG;

    float pA[4], pB[4];
#pragma unroll
    for (int i = 0; i < 4; i++) {
        pA[i] = on ? bpA[i * tstride] : 0.f;
        pB[i] = on ? bpB[i * tstride] : 0.f;
    }

#pragma unroll 1
    for (int t0 = 0; t0 < SN; t0 += 4) {
        float nA[4], nB[4];
        if (t0 + 4 < SN) {
#pragma unroll
            for (int i = 0; i < 4; i++) {       // batch 8 LDGs -> MLP 8
                nA[i] = on ? bpA[(t0 + 4 + i) * tstride] : 0.f;
                nB[i] = on ? bpB[(t0 + 4 + i) * tstride] : 0.f;
            }
        } else {
#pragma unroll
            for (int i = 0; i < 4; i++) { nA[i] = 0.f; nB[i] = 0.f; }
        }
#pragma unroll
        for (int tt = 0; tt < 4; tt++) {
            float aA = pA[tt], aB = pB[tt];
#pragma unroll
            for (int j = 0; j < HH; j++) {
                float hj = __shfl_sync(0xffffffffu, hx, j, 16);
                aA = fmaf(hj, wA[j], aA);
                aB = fmaf(hj, wB[j], aB);
            }
            float cA = __cosf(aA), cB = __cosf(aB);
            float dA = (l == 0) ? 1.f : cA;
            float dB = (l == 0) ? 1.f : cB;
#pragma unroll
            for (int off = 1; off < 16; off <<= 1) {
                float vA = __shfl_up_sync(0xffffffffu, dA, off, 16);
                float vB = __shfl_up_sync(0xffffffffu, dB, off, 16);
                if (l >= off) { dA *= vA; dB *= vB; }
            }
            float c0A = __shfl_sync(0xffffffffu, cA, 0, 16);
            float c0B = __shfl_sync(0xffffffffu, cB, 0, 16);
            float q9A = __shfl_sync(0xffffffffu, dA, HH - 1, 16);
            float q9B = __shfl_sync(0xffffffffu, dB, HH - 1, 16);
            float qA = (l == 0) ? q9A : c0A * dA;
            float qB = (l == 0) ? q9B : c0B * dB;

            float eA   = __expf(-sa * qA);
            float actA = fmaf(ca, __fdividef(1.f, 1.f + eA), cbk);  // f / g
            float eB   = __expf(-qB);
            float actB = __fdividef(1.f, 1.f + eB);                 // i / o

            float xA = __shfl_xor_sync(0xffffffffu, actA, 16);
            float xB = __shfl_xor_sync(0xffffffffu, actB, 16);
            float f  = grp ? xA   : actA;
            float ii = grp ? xB   : actB;
            float gg = grp ? actA : xA;
            float o  = grp ? actB : xB;

            cx = fmaf(f, cx, ii * gg);
            float e2 = __expf(-2.f * cx);
            float th = fmaf(2.f, __fdividef(1.f, 1.f + e2), -1.f);  // tanh(cx)
            hx = o * th;

            if (on && grp == 0) g_hx[((size_t)(t0 + tt) * SN + b) * HH + l] = hx;
        }
#pragma unroll
        for (int i = 0; i < 4; i++) { pA[i] = nA[i]; pB[i] = nB[i]; }
    }
}

// =========================================================================
// Phase C: logits = hx @ W_out + b_out, then log_softmax over T=50.
// =========================================================================
__global__ __launch_bounds__(128) void phaseC_kernel(
    const float* __restrict__ Wout, const float* __restrict__ bout,
    float* __restrict__ out)
{
    __shared__ float sW[HH * TT];
    __shared__ float sbv[TT];
    const int tid = threadIdx.x;
    for (int i = tid; i < HH * TT; i += 128) sW[i] = Wout[i];
    for (int i = tid; i < TT;      i += 128) sbv[i] = bout[i];
    __syncthreads();

    const int row = blockIdx.x * 128 + tid;
    float h[HH];
#pragma unroll
    for (int j = 0; j < HH; j++) h[j] = g_hx[(size_t)row * HH + j];

    float lg[TT];
#pragma unroll
    for (int c = 0; c < TT; c++) {
        float s = sbv[c];
#pragma unroll
        for (int j = 0; j < HH; j++) s = fmaf(h[j], sW[j * TT + c], s);
        lg[c] = s;
    }
    float m = lg[0];
#pragma unroll
    for (int c = 1; c < TT; c++) m = fmaxf(m, lg[c]);
    float sum = 0.f;
#pragma unroll
    for (int c = 0; c < TT; c++) sum += __expf(lg[c] - m);
    float ls = m + __logf(sum);

    float2* op = (float2*)(out + (size_t)row * TT);
#pragma unroll
    for (int c = 0; c < TT / 2; c++)
        op[c] = make_float2(lg[2 * c] - ls, lg[2 * c + 1] - ls);
}

// =========================================================================
extern "C" void kernel_launch(void* const* d_in, const int* in_sizes, int n_in,
                              void* d_out, int out_size)
{
    const int*   tok   = (const int*)d_in[0];     // sentence (256,256) int32
    const float* emb   = (const float*)d_in[1];   // (V, E)
    const float* Wg    = (const float*)d_in[2];   // (4, E+H, H)
    const float* bg    = (const float*)d_in[3];   // (4, H)
    const float* theta = (const float*)d_in[4];   // (4, H)
    const float* Wout  = (const float*)d_in[5];   // (H, T)
    const float* bout  = (const float*)d_in[6];   // (T)
    float* out = (float*)d_out;                   // (256,256,50) float32

    cudaFuncSetAttribute(phaseA_kernel, cudaFuncAttributeMaxDynamicSharedMemorySize, SM_TOT);

    prepB_kernel<<<(NCH * NG * BK + 255) / 256, 256>>>(Wg);
    phaseA_kernel<<<NP / MT, ATHREADS, SM_TOT>>>(tok, emb, bg, theta);
    phaseB_kernel<<<SN, 32>>>(Wg);
    phaseC_kernel<<<NP / 128, 128>>>(Wout, bout, out);
}

// round 6
// speedup vs baseline: 2.3423x; 1.6983x over previous
#include <cuda_runtime.h>
#include <cstdint>

// Problem constants
#define SN 256        // batch == seq_len
#define EE 1024       // embedding dim
#define HH 10         // hidden dim
#define NG 40         // 4 gates * H
#define TT 50         // tagset size
#define NP (SN*SN)    // 65536 rows (t,b)
#define WG_STRIDE 10340  // (E+H)*H per gate

// Phase A tiling (mma.sync m16n8k8 tf32)
#define BK 32         // k chunk
#define MT 128        // rows per block
#define ATHREADS 128  // 4 warps: each 2 m-tiles x 5 n-tiles
#define NCH (EE/BK)   // 32 chunks
#define AST 36        // padded row stride (floats) -> conflict-free fragment loads
#define A_STAGE_F (MT*AST)   // 4608 floats
#define B_STAGE_F (NG*AST)   // 1440 floats

// smem layout (bytes)
#define SM_STOK 0
#define SM_A    1024
#define SM_B    (SM_A + 2*A_STAGE_F*4)      // 37888
#define SM_TOT  (SM_B + 2*B_STAGE_F*4)      // 49408

// Scratch (no allocations allowed -> device globals)
__device__ float g_base[(size_t)NP * NG];   // x@Wx + bg + theta
__device__ float g_hx[(size_t)NP * HH];     // hx outputs of the scan
__device__ __align__(16) float g_Bt[NCH * NG * BK];  // B transposed per chunk: [ch][n][k], tf32-rounded

// ---------- helpers ----------
__device__ __forceinline__ void cp16(uint32_t dst, const void* src) {
    asm volatile("cp.async.cg.shared.global [%0], [%1], 16;" :: "r"(dst), "l"(src) : "memory");
}
__device__ __forceinline__ void hmma_tf32(float* d, uint32_t a0, uint32_t a1, uint32_t a2, uint32_t a3,
                                          uint32_t b0, uint32_t b1) {
    asm volatile(
        "mma.sync.aligned.m16n8k8.row.col.f32.tf32.tf32.f32 "
        "{%0,%1,%2,%3}, {%4,%5,%6,%7}, {%8,%9}, {%0,%1,%2,%3};"
        : "+f"(d[0]), "+f"(d[1]), "+f"(d[2]), "+f"(d[3])
        : "r"(a0), "r"(a1), "r"(a2), "r"(a3), "r"(b0), "r"(b1));
}

// =========================================================================
// B pre-transpose + tf32 round: g_Bt[ch][n][k]
// =========================================================================
__global__ __launch_bounds__(256) void prepB_kernel(const float* __restrict__ Wg)
{
    int idx = blockIdx.x * 256 + threadIdx.x;          // 0..40959
    if (idx >= NCH * NG * BK) return;
    int ch = idx / (NG * BK);
    int r  = idx % (NG * BK);
    int n  = r / BK, k = r % BK;
    float v = Wg[(n / HH) * WG_STRIDE + (ch * BK + k) * HH + (n % HH)];
    uint32_t u;
    asm("cvt.rna.tf32.f32 %0, %1;" : "=r"(u) : "f"(v));
    g_Bt[idx] = __uint_as_float(u);
}

// =========================================================================
// Phase A: gathered skinny GEMM on mma.sync tf32 (HMMA).
// 128 rows x 40 cols per CTA. A: k-major smem, stride 36 floats -> all
// fragment loads hit banks 4g+t (conflict-free). B: [n][k] stride 36.
// Double-buffered depth-1 cp.async pipeline.
// =========================================================================
extern __shared__ char smem_raw[];

__global__ __launch_bounds__(ATHREADS, 4) void phaseA_kernel(
    const int* __restrict__ tok, const float* __restrict__ emb,
    const float* __restrict__ bg, const float* __restrict__ theta)
{
    int*   stok = (int*)(smem_raw + SM_STOK);
    float* sA   = (float*)(smem_raw + SM_A);
    float* sB   = (float*)(smem_raw + SM_B);

    const int tid = threadIdx.x;
    const int rowbase = blockIdx.x * MT;

    if (tid < MT) stok[tid] = tok[rowbase + tid];
    __syncthreads();

    const int wid  = tid >> 5, lane = tid & 31;
    const int g    = lane >> 2, t = lane & 3;
    const int w32  = wid * 32;

    float acc[2][5][4];
#pragma unroll
    for (int m = 0; m < 2; m++)
#pragma unroll
        for (int n = 0; n < 5; n++)
#pragma unroll
            for (int q = 0; q < 4; q++) acc[m][n][q] = 0.f;

    const uint32_t sA_base = (uint32_t)__cvta_generic_to_shared(sA);
    const uint32_t sB_base = (uint32_t)__cvta_generic_to_shared(sB);

    auto issue_chunk = [&](int ch) {
        const int s = ch & 1;
        const uint32_t abase = sA_base + (uint32_t)(s * A_STAGE_F * 4);
        // A gather: 1024 16B chunks, 8/thread
#pragma unroll
        for (int it = 0; it < 8; it++) {
            int idx = it * ATHREADS + tid;
            int row = idx >> 3, c = idx & 7;
            cp16(abase + (uint32_t)(row * (AST * 4) + (c << 4)),
                 emb + (size_t)stok[row] * EE + ch * BK + (c << 2));
        }
        // B: 320 16B chunks from pre-transposed tf32 global
        const uint32_t bbase = sB_base + (uint32_t)(s * B_STAGE_F * 4);
        const float* bsrc = g_Bt + ch * (NG * BK);
#pragma unroll
        for (int it = 0; it < 3; it++) {
            int i = it * ATHREADS + tid;
            if (i < NG * 8) {
                int n = i >> 3, kq = i & 7;
                cp16(bbase + (uint32_t)(n * (AST * 4) + (kq << 4)), bsrc + (i << 2));
            }
        }
        asm volatile("cp.async.commit_group;" ::: "memory");
    };

    issue_chunk(0);

    for (int ch = 0; ch < NCH; ch++) {
        asm volatile("cp.async.wait_group 0;" ::: "memory");
        __syncthreads();
        if (ch + 1 < NCH) issue_chunk(ch + 1);

        const int s = ch & 1;
        const uint32_t* A = (const uint32_t*)(sA + s * A_STAGE_F);
        const uint32_t* B = (const uint32_t*)(sB + s * B_STAGE_F);
#pragma unroll
        for (int s4 = 0; s4 < 4; s4++) {
            uint32_t b0[5], b1[5];
#pragma unroll
            for (int n = 0; n < 5; n++) {
                const uint32_t* bp = B + (n * 8 + g) * AST + s4 * 8 + t;
                b0[n] = bp[0];
                b1[n] = bp[4];
            }
#pragma unroll
            for (int m = 0; m < 2; m++) {
                const uint32_t* ap = A + (w32 + m * 16 + g) * AST + s4 * 8 + t;
                uint32_t a0 = ap[0];
                uint32_t a2 = ap[4];
                uint32_t a1 = ap[8 * AST];
                uint32_t a3 = ap[8 * AST + 4];
#pragma unroll
                for (int n = 0; n < 5; n++)
                    hmma_tf32(acc[m][n], a0, a1, a2, a3, b0[n], b1[n]);
            }
        }
    }

    // epilogue: add bg + theta, store (D frag: rows g/g+8, cols 2t,2t+1)
    float cbx[5], cby[5];
#pragma unroll
    for (int n = 0; n < 5; n++) {
        int col = n * 8 + 2 * t;
        cbx[n] = bg[col] + theta[col];
        cby[n] = bg[col + 1] + theta[col + 1];
    }
#pragma unroll
    for (int m = 0; m < 2; m++) {
        int row0 = rowbase + w32 + m * 16 + g;
#pragma unroll
        for (int n = 0; n < 5; n++) {
            int col = n * 8 + 2 * t;
            *(float2*)(g_base + (size_t)row0 * NG + col) =
                make_float2(acc[m][n][0] + cbx[n], acc[m][n][1] + cby[n]);
            *(float2*)(g_base + (size_t)(row0 + 8) * NG + col) =
                make_float2(acc[m][n][2] + cbx[n], acc[m][n][3] + cby[n]);
        }
    }
}

// =========================================================================
// Phase B: one LSTM chain per warp. Lanes 0-15: gates (f,i); lanes 16-31:
// gates (g,o). Dual-register half-warp scans; 4-step-deep LDG prefetch.
// =========================================================================
__global__ __launch_bounds__(32) void phaseB_kernel(const float* __restrict__ Wg)
{
    const int lane = threadIdx.x;
    const int grp  = lane >> 4;          // 0: f,i   1: g,o
    const int l    = lane & 15;
    const int b    = blockIdx.x;
    const bool on  = (l < HH);

    const int gA = grp ? 2 : 0;          // f or g
    const int gB = grp ? 3 : 1;          // i or o

    float wA[HH], wB[HH];
#pragma unroll
    for (int j = 0; j < HH; j++) {
        wA[j] = on ? Wg[gA * WG_STRIDE + (EE + j) * HH + l] : 0.f;
        wB[j] = on ? Wg[gB * WG_STRIDE + (EE + j) * HH + l] : 0.f;
    }

    const float sa  = grp ? 2.f : 1.f;
    const float ca  = grp ? 2.f : 1.f;
    const float cbk = grp ? -1.f : 0.f;

    float hx = 0.f, cx = 0.f;
    const float* bpA = g_base + (size_t)b * NG + gA * 10 + l;
    const float* bpB = g_base + (size_t)b * NG + gB * 10 + l;
    const size_t tstride = (size_t)SN * NG;

    float pA[4], pB[4];
#pragma unroll
    for (int i = 0; i < 4; i++) {
        pA[i] = on ? bpA[i * tstride] : 0.f;
        pB[i] = on ? bpB[i * tstride] : 0.f;
    }

#pragma unroll 1
    for (int t0 = 0; t0 < SN; t0 += 4) {
        float nA[4], nB[4];
        if (t0 + 4 < SN) {
#pragma unroll
            for (int i = 0; i < 4; i++) {       // batch 8 LDGs -> MLP 8
                nA[i] = on ? bpA[(t0 + 4 + i) * tstride] : 0.f;
                nB[i] = on ? bpB[(t0 + 4 + i) * tstride] : 0.f;
            }
        } else {
#pragma unroll
            for (int i = 0; i < 4; i++) { nA[i] = 0.f; nB[i] = 0.f; }
        }
#pragma unroll
        for (int tt = 0; tt < 4; tt++) {
            float aA = pA[tt], aB = pB[tt];
#pragma unroll
            for (int j = 0; j < HH; j++) {
                float hj = __shfl_sync(0xffffffffu, hx, j, 16);
                aA = fmaf(hj, wA[j], aA);
                aB = fmaf(hj, wB[j], aB);
            }
            float cA = __cosf(aA), cB = __cosf(aB);
            float dA = (l == 0) ? 1.f : cA;
            float dB = (l == 0) ? 1.f : cB;
#pragma unroll
            for (int off = 1; off < 16; off <<= 1) {
                float vA = __shfl_up_sync(0xffffffffu, dA, off, 16);
                float vB = __shfl_up_sync(0xffffffffu, dB, off, 16);
                if (l >= off) { dA *= vA; dB *= vB; }
            }
            float c0A = __shfl_sync(0xffffffffu, cA, 0, 16);
            float c0B = __shfl_sync(0xffffffffu, cB, 0, 16);
            float q9A = __shfl_sync(0xffffffffu, dA, HH - 1, 16);
            float q9B = __shfl_sync(0xffffffffu, dB, HH - 1, 16);
            float qA = (l == 0) ? q9A : c0A * dA;
            float qB = (l == 0) ? q9B : c0B * dB;

            float eA   = __expf(-sa * qA);
            float actA = fmaf(ca, __fdividef(1.f, 1.f + eA), cbk);  // f / g
            float eB   = __expf(-qB);
            float actB = __fdividef(1.f, 1.f + eB);                 // i / o

            float xA = __shfl_xor_sync(0xffffffffu, actA, 16);
            float xB = __shfl_xor_sync(0xffffffffu, actB, 16);
            float f  = grp ? xA   : actA;
            float ii = grp ? xB   : actB;
            float gg = grp ? actA : xA;
            float o  = grp ? actB : xB;

            cx = fmaf(f, cx, ii * gg);
            float e2 = __expf(-2.f * cx);
            float th = fmaf(2.f, __fdividef(1.f, 1.f + e2), -1.f);  // tanh(cx)
            hx = o * th;

            if (on && grp == 0) g_hx[((size_t)(t0 + tt) * SN + b) * HH + l] = hx;
        }
#pragma unroll
        for (int i = 0; i < 4; i++) { pA[i] = nA[i]; pB[i] = nB[i]; }
    }
}

// =========================================================================
// Phase C: logits + log_softmax. 2 lanes per row (25 cols each) -> 2x threads.
// =========================================================================
__global__ __launch_bounds__(128) void phaseC_kernel(
    const float* __restrict__ Wout, const float* __restrict__ bout,
    float* __restrict__ out)
{
    __shared__ float sW[HH * TT];
    __shared__ float sbv[TT];
    const int tid = threadIdx.x;
    for (int i = tid; i < HH * TT; i += 128) sW[i] = Wout[i];
    for (int i = tid; i < TT;      i += 128) sbv[i] = bout[i];
    __syncthreads();

    const int half = tid & 1;                       // 0: cols 0-24, 1: cols 25-49
    const int row  = blockIdx.x * 64 + (tid >> 1);
    const int c0   = half * 25;

    float h[HH];
#pragma unroll
    for (int j = 0; j < HH; j++) h[j] = g_hx[(size_t)row * HH + j];

    float lg[25];
#pragma unroll
    for (int c = 0; c < 25; c++) {
        float s = sbv[c0 + c];
#pragma unroll
        for (int j = 0; j < HH; j++) s = fmaf(h[j], sW[j * TT + c0 + c], s);
        lg[c] = s;
    }
    float m = lg[0];
#pragma unroll
    for (int c = 1; c < 25; c++) m = fmaxf(m, lg[c]);
    m = fmaxf(m, __shfl_xor_sync(0xffffffffu, m, 1));
    float sum = 0.f;
#pragma unroll
    for (int c = 0; c < 25; c++) sum += __expf(lg[c] - m);
    sum += __shfl_xor_sync(0xffffffffu, sum, 1);
    float ls = m + __logf(sum);

    float* op = out + (size_t)row * TT + c0;
#pragma unroll
    for (int c = 0; c < 25; c++) op[c] = lg[c] - ls;
}

// =========================================================================
extern "C" void kernel_launch(void* const* d_in, const int* in_sizes, int n_in,
                              void* d_out, int out_size)
{
    const int*   tok   = (const int*)d_in[0];     // sentence (256,256) int32
    const float* emb   = (const float*)d_in[1];   // (V, E)
    const float* Wg    = (const float*)d_in[2];   // (4, E+H, H)
    const float* bg    = (const float*)d_in[3];   // (4, H)
    const float* theta = (const float*)d_in[4];   // (4, H)
    const float* Wout  = (const float*)d_in[5];   // (H, T)
    const float* bout  = (const float*)d_in[6];   // (T)
    float* out = (float*)d_out;                   // (256,256,50) float32

    cudaFuncSetAttribute(phaseA_kernel, cudaFuncAttributeMaxDynamicSharedMemorySize, SM_TOT);

    prepB_kernel<<<(NCH * NG * BK + 255) / 256, 256>>>(Wg);
    phaseA_kernel<<<NP / MT, ATHREADS, SM_TOT>>>(tok, emb, bg, theta);
    phaseB_kernel<<<SN, 32>>>(Wg);
    phaseC_kernel<<<NP / 64, 128>>>(Wout, bout, out);
}